// round 3
// baseline (speedup 1.0000x reference)
#include <cuda_runtime.h>
#include <cuda_bf16.h>
#include <math.h>

#define B_ 8
#define N_ 2048
#define D_ 128
#define V_ 32
#define E_ 32   // D/4

// ---------------- scratch (device globals; no allocation allowed) ----------
__device__ float g_ctx [B_ * V_ * D_];      // per-variable mean context
__device__ float g_graw[B_ * N_];
__device__ float g_u   [B_ * N_];           // exp(t/tau)*g_raw
__device__ float g_v   [B_ * N_];           // exp(-t/tau)*mask
__device__ float g_al  [B_ * N_];           // alpha per cell
__device__ float g_epre[B_ * N_ * E_];      // e_n before refractory scaling

// ---------------- K1: per-(b,e) mean context --------------------------------
// grid = B*V blocks, 128 threads (= D). Build match list in smem, then
// coalesced accumulate over matching obs rows.
__global__ void k1_context(const float* __restrict__ obs,
                           const int*   __restrict__ idx) {
    const int b = blockIdx.x / V_;
    const int e = blockIdx.x % V_;
    __shared__ int s_list[N_];
    __shared__ int s_cnt;
    if (threadIdx.x == 0) s_cnt = 0;
    __syncthreads();
    for (int i = threadIdx.x; i < N_; i += blockDim.x) {
        if (idx[b * N_ + i] == e) {
            int p = atomicAdd(&s_cnt, 1);
            s_list[p] = i;
        }
    }
    __syncthreads();
    const int cnt = s_cnt;
    const int d = threadIdx.x;     // blockDim.x == D_
    float acc = 0.0f;
    for (int k = 0; k < cnt; k++) {
        acc += obs[((size_t)(b * N_ + s_list[k])) * D_ + d];
    }
    float c = fmaxf((float)cnt, 1.0f);
    g_ctx[(b * V_ + e) * D_ + d] = acc / c;
}

// ---------------- K2: per-cell membrane / gate / event projection -----------
// grid = B*N/8 blocks, 256 threads = 8 warps, one cell per warp.
__global__ void k2_cell(const float* __restrict__ obs,
                        const float* __restrict__ mask,
                        const int*   __restrict__ idx,
                        const float* __restrict__ tn,
                        const float* __restrict__ Wm,
                        const float* __restrict__ bm,
                        const float* __restrict__ We,
                        const float* __restrict__ be,
                        const float* __restrict__ ltau,
                        const float* __restrict__ lal) {
    __shared__ float s_in[8][2 * D_];
    const int warp = threadIdx.x >> 5;
    const int lane = threadIdx.x & 31;
    const int cell = blockIdx.x * 8 + warp;
    const int b = cell / N_;
    const int n = cell % N_;
    const int e = idx[b * N_ + n];

    const float4* o4 = (const float4*)(obs + (size_t)cell * D_);
    const float4* c4 = (const float4*)(g_ctx + (size_t)(b * V_ + e) * D_);
    float4 o = o4[lane];
    float4 c = c4[lane];
    float4 dv = make_float4(o.x - c.x, o.y - c.y, o.z - c.z, o.w - c.w);

    s_in[warp][lane * 4 + 0] = o.x;
    s_in[warp][lane * 4 + 1] = o.y;
    s_in[warp][lane * 4 + 2] = o.z;
    s_in[warp][lane * 4 + 3] = o.w;
    s_in[warp][D_ + lane * 4 + 0] = dv.x;
    s_in[warp][D_ + lane * 4 + 1] = dv.y;
    s_in[warp][D_ + lane * 4 + 2] = dv.z;
    s_in[warp][D_ + lane * 4 + 3] = dv.w;

    // membrane = mem_in . W_mem + b_mem  (warp reduction)
    const float4* wm4 = (const float4*)Wm;
    float4 w0 = wm4[lane];
    float4 w1 = wm4[32 + lane];
    float part = o.x * w0.x + o.y * w0.y + o.z * w0.z + o.w * w0.w
               + dv.x * w1.x + dv.y * w1.y + dv.z * w1.z + dv.w * w1.w;
    #pragma unroll
    for (int s = 16; s > 0; s >>= 1)
        part += __shfl_xor_sync(0xffffffffu, part, s);
    const float membrane = part + bm[0];

    const float mk = mask[cell];
    const float g  = mk / (1.0f + expf(-membrane));   // sigmoid * mask

    if (lane == 0) {
        const float t   = tn[cell];
        const float tau = expf(ltau[e]);
        g_graw[cell] = g;
        g_u[cell]    = expf(t / tau) * g;
        g_v[cell]    = expf(-t / tau) * mk;
        g_al[cell]   = expf(lal[e]);
    }
    __syncwarp();

    // e_pre[j] = (mem_in . W_evt[:,j] + b_evt[j]) * g    (lane j = channel j)
    float acc = be[lane];
    #pragma unroll 4
    for (int d = 0; d < 2 * D_; d++) {
        acc += s_in[warp][d] * We[d * E_ + lane];
    }
    g_epre[(size_t)cell * E_ + lane] = acc * g;
}

// ---------------- K3: refractory inhibition + outputs ------------------------
// grid = B * (N/128) blocks, 512 threads. Each block handles 128 n's; four
// thread-slices each scan 512 of the 2048 m's (batch-resident in smem),
// predicate folded into a single 64-bit ordered key.
#define K3_TPB 512
#define K3_NPB 128
#define K3_SLICES 4
#define K3_MS (N_ / K3_SLICES)   // 512

__global__ void k3_refr(const int*   __restrict__ idx,
                        const float* __restrict__ tn,
                        float*       __restrict__ out) {
    const int b  = blockIdx.x / (N_ / K3_NPB);
    const int nb = blockIdx.x % (N_ / K3_NPB);
    __shared__ long long s_key[N_];          // (idx<<32) | float_bits(t)
    __shared__ float     s_u[N_];
    __shared__ float     s_part[K3_SLICES][K3_NPB];
    __shared__ float     s_gr[K3_NPB];

    for (int i = threadIdx.x; i < N_; i += K3_TPB) {
        const int   vi = idx[b * N_ + i];
        const float t  = tn[b * N_ + i];
        s_key[i] = ((long long)vi << 32) | (long long)(unsigned)__float_as_uint(t);
        s_u[i]   = g_u[b * N_ + i];
    }
    __syncthreads();

    const int nl    = threadIdx.x & (K3_NPB - 1);   // local n   0..127
    const int sl    = threadIdx.x >> 7;             // slice     0..3
    const int n     = nb * K3_NPB + nl;
    const int cell  = b * N_ + n;

    const long long hik = s_key[n];                  // (mi<<32)|tbits(n)
    const long long lok = hik & 0xffffffff00000000ll;

    const int m0 = sl * K3_MS;
    float a0 = 0.f, a1 = 0.f, a2 = 0.f, a3 = 0.f;
    #pragma unroll 4
    for (int m = m0; m < m0 + K3_MS; m += 4) {
        long long k0 = s_key[m + 0], k1 = s_key[m + 1];
        long long k2 = s_key[m + 2], k3 = s_key[m + 3];
        a0 += (k0 >= lok && k0 < hik) ? s_u[m + 0] : 0.f;
        a1 += (k1 >= lok && k1 < hik) ? s_u[m + 1] : 0.f;
        a2 += (k2 >= lok && k2 < hik) ? s_u[m + 2] : 0.f;
        a3 += (k3 >= lok && k3 < hik) ? s_u[m + 3] : 0.f;
    }
    s_part[sl][nl] = (a0 + a1) + (a2 + a3);
    __syncthreads();

    if (threadIdx.x < K3_NPB) {
        const float sum = (s_part[0][nl] + s_part[1][nl])
                        + (s_part[2][nl] + s_part[3][nl]);
        const float inh  = g_v[cell] * sum;
        const float gr   = 1.0f - tanhf(g_al[cell] * inh);
        out[cell]        = g_graw[cell] * gr;        // g_n
        s_gr[nl]         = gr;
    }
    __syncthreads();

    // coalesced e_n = e_pre * g_refr  (128 cells * 32 ch = 4096 elems)
    const int base_cell = b * N_ + nb * K3_NPB;
    float* oe = out + (size_t)B_ * N_;
    const size_t base = (size_t)base_cell * E_;
    for (int k = threadIdx.x; k < K3_NPB * E_; k += K3_TPB) {
        oe[base + k] = g_epre[base + k] * s_gr[k >> 5];
    }
}

extern "C" void kernel_launch(void* const* d_in, const int* in_sizes, int n_in,
                              void* d_out, int out_size) {
    const float* obs  = (const float*)d_in[0];
    const float* mask = (const float*)d_in[1];
    // d_in[2] = variable_incidence_matrix: redundant (one_hot of idx), unused
    const int*   idx  = (const int*)  d_in[3];
    const float* tn   = (const float*)d_in[4];
    const float* Wm   = (const float*)d_in[5];
    const float* bm   = (const float*)d_in[6];
    const float* We   = (const float*)d_in[7];
    const float* be   = (const float*)d_in[8];
    const float* ltau = (const float*)d_in[9];
    const float* lal  = (const float*)d_in[10];
    float* out = (float*)d_out;

    k1_context<<<B_ * V_, 128>>>(obs, idx);
    k2_cell<<<(B_ * N_) / 8, 256>>>(obs, mask, idx, tn, Wm, bm, We, be, ltau, lal);
    k3_refr<<<B_ * (N_ / K3_NPB), K3_TPB>>>(idx, tn, out);
}

// round 4
// speedup vs baseline: 1.0084x; 1.0084x over previous
#include <cuda_runtime.h>
#include <cuda_bf16.h>
#include <math.h>

#define B_ 8
#define N_ 2048
#define D_ 128
#define V_ 32
#define E_ 32   // D/4

// ---------------- scratch (device globals; no allocation allowed) ----------
__device__ float g_ctx [B_ * V_ * D_];      // per-variable mean context
__device__ float g_graw[B_ * N_];
__device__ float g_u   [B_ * N_];           // exp(t/tau)*g_raw
__device__ float g_v   [B_ * N_];           // exp(-t/tau)*mask
__device__ float g_al  [B_ * N_];           // alpha per cell
__device__ float g_epre[B_ * N_ * E_];      // e_n before refractory scaling

// ---------------- K1: per-(b,e) mean context --------------------------------
// grid = B*V blocks, 128 threads (= D). Build match list in smem, then
// coalesced accumulate over matching obs rows.
__global__ void k1_context(const float* __restrict__ obs,
                           const int*   __restrict__ idx) {
    const int b = blockIdx.x / V_;
    const int e = blockIdx.x % V_;
    __shared__ int s_list[N_];
    __shared__ int s_cnt;
    if (threadIdx.x == 0) s_cnt = 0;
    __syncthreads();
    for (int i = threadIdx.x; i < N_; i += blockDim.x) {
        if (idx[b * N_ + i] == e) {
            int p = atomicAdd(&s_cnt, 1);
            s_list[p] = i;
        }
    }
    __syncthreads();
    const int cnt = s_cnt;
    const int d = threadIdx.x;     // blockDim.x == D_
    float acc = 0.0f;
    for (int k = 0; k < cnt; k++) {
        acc += obs[((size_t)(b * N_ + s_list[k])) * D_ + d];
    }
    float c = fmaxf((float)cnt, 1.0f);
    g_ctx[(b * V_ + e) * D_ + d] = acc / c;
}

// ---------------- K2: per-cell membrane / gate / event projection -----------
// grid = B*N/8 blocks, 256 threads = 8 warps, one cell per warp.
__global__ void k2_cell(const float* __restrict__ obs,
                        const float* __restrict__ mask,
                        const int*   __restrict__ idx,
                        const float* __restrict__ tn,
                        const float* __restrict__ Wm,
                        const float* __restrict__ bm,
                        const float* __restrict__ We,
                        const float* __restrict__ be,
                        const float* __restrict__ ltau,
                        const float* __restrict__ lal) {
    __shared__ float s_in[8][2 * D_];
    const int warp = threadIdx.x >> 5;
    const int lane = threadIdx.x & 31;
    const int cell = blockIdx.x * 8 + warp;
    const int b = cell / N_;
    const int n = cell % N_;
    const int e = idx[b * N_ + n];

    const float4* o4 = (const float4*)(obs + (size_t)cell * D_);
    const float4* c4 = (const float4*)(g_ctx + (size_t)(b * V_ + e) * D_);
    float4 o = o4[lane];
    float4 c = c4[lane];
    float4 dv = make_float4(o.x - c.x, o.y - c.y, o.z - c.z, o.w - c.w);

    s_in[warp][lane * 4 + 0] = o.x;
    s_in[warp][lane * 4 + 1] = o.y;
    s_in[warp][lane * 4 + 2] = o.z;
    s_in[warp][lane * 4 + 3] = o.w;
    s_in[warp][D_ + lane * 4 + 0] = dv.x;
    s_in[warp][D_ + lane * 4 + 1] = dv.y;
    s_in[warp][D_ + lane * 4 + 2] = dv.z;
    s_in[warp][D_ + lane * 4 + 3] = dv.w;

    // membrane = mem_in . W_mem + b_mem  (warp reduction)
    const float4* wm4 = (const float4*)Wm;
    float4 w0 = wm4[lane];
    float4 w1 = wm4[32 + lane];
    float part = o.x * w0.x + o.y * w0.y + o.z * w0.z + o.w * w0.w
               + dv.x * w1.x + dv.y * w1.y + dv.z * w1.z + dv.w * w1.w;
    #pragma unroll
    for (int s = 16; s > 0; s >>= 1)
        part += __shfl_xor_sync(0xffffffffu, part, s);
    const float membrane = part + bm[0];

    const float mk = mask[cell];
    const float g  = mk / (1.0f + expf(-membrane));   // sigmoid * mask

    if (lane == 0) {
        const float t   = tn[cell];
        const float tau = expf(ltau[e]);
        g_graw[cell] = g;
        g_u[cell]    = expf(t / tau) * g;
        g_v[cell]    = expf(-t / tau) * mk;
        g_al[cell]   = expf(lal[e]);
    }
    __syncwarp();

    // e_pre[j] = (mem_in . W_evt[:,j] + b_evt[j]) * g    (lane j = channel j)
    float acc = be[lane];
    #pragma unroll 4
    for (int d = 0; d < 2 * D_; d++) {
        acc += s_in[warp][d] * We[d * E_ + lane];
    }
    g_epre[(size_t)cell * E_ + lane] = acc * g;
}

// ---------------- K3: refractory inhibition + outputs ------------------------
// grid = B * (N/128) blocks, 512 threads. Each block handles 128 n's; four
// thread-slices each scan 512 of the 2048 m's (batch-resident in smem),
// predicate folded into a single 64-bit ordered key.
#define K3_TPB 512
#define K3_NPB 128
#define K3_SLICES 4
#define K3_MS (N_ / K3_SLICES)   // 512

__global__ void k3_refr(const int*   __restrict__ idx,
                        const float* __restrict__ tn,
                        float*       __restrict__ out) {
    const int b  = blockIdx.x / (N_ / K3_NPB);
    const int nb = blockIdx.x % (N_ / K3_NPB);
    __shared__ long long s_key[N_];          // (idx<<32) | float_bits(t)
    __shared__ float     s_u[N_];
    __shared__ float     s_part[K3_SLICES][K3_NPB];
    __shared__ float     s_gr[K3_NPB];

    for (int i = threadIdx.x; i < N_; i += K3_TPB) {
        const int   vi = idx[b * N_ + i];
        const float t  = tn[b * N_ + i];
        s_key[i] = ((long long)vi << 32) | (long long)(unsigned)__float_as_uint(t);
        s_u[i]   = g_u[b * N_ + i];
    }
    __syncthreads();

    const int nl    = threadIdx.x & (K3_NPB - 1);   // local n   0..127
    const int sl    = threadIdx.x >> 7;             // slice     0..3
    const int n     = nb * K3_NPB + nl;
    const int cell  = b * N_ + n;

    const long long hik = s_key[n];                  // (mi<<32)|tbits(n)
    const long long lok = hik & 0xffffffff00000000ll;

    const int m0 = sl * K3_MS;
    float a0 = 0.f, a1 = 0.f, a2 = 0.f, a3 = 0.f;
    #pragma unroll 4
    for (int m = m0; m < m0 + K3_MS; m += 4) {
        long long k0 = s_key[m + 0], k1 = s_key[m + 1];
        long long k2 = s_key[m + 2], k3 = s_key[m + 3];
        a0 += (k0 >= lok && k0 < hik) ? s_u[m + 0] : 0.f;
        a1 += (k1 >= lok && k1 < hik) ? s_u[m + 1] : 0.f;
        a2 += (k2 >= lok && k2 < hik) ? s_u[m + 2] : 0.f;
        a3 += (k3 >= lok && k3 < hik) ? s_u[m + 3] : 0.f;
    }
    s_part[sl][nl] = (a0 + a1) + (a2 + a3);
    __syncthreads();

    if (threadIdx.x < K3_NPB) {
        const float sum = (s_part[0][nl] + s_part[1][nl])
                        + (s_part[2][nl] + s_part[3][nl]);
        const float inh  = g_v[cell] * sum;
        const float gr   = 1.0f - tanhf(g_al[cell] * inh);
        out[cell]        = g_graw[cell] * gr;        // g_n
        s_gr[nl]         = gr;
    }
    __syncthreads();

    // coalesced e_n = e_pre * g_refr  (128 cells * 32 ch = 4096 elems)
    const int base_cell = b * N_ + nb * K3_NPB;
    float* oe = out + (size_t)B_ * N_;
    const size_t base = (size_t)base_cell * E_;
    for (int k = threadIdx.x; k < K3_NPB * E_; k += K3_TPB) {
        oe[base + k] = g_epre[base + k] * s_gr[k >> 5];
    }
}

extern "C" void kernel_launch(void* const* d_in, const int* in_sizes, int n_in,
                              void* d_out, int out_size) {
    const float* obs  = (const float*)d_in[0];
    const float* mask = (const float*)d_in[1];
    // d_in[2] = variable_incidence_matrix: redundant (one_hot of idx), unused
    const int*   idx  = (const int*)  d_in[3];
    const float* tn   = (const float*)d_in[4];
    const float* Wm   = (const float*)d_in[5];
    const float* bm   = (const float*)d_in[6];
    const float* We   = (const float*)d_in[7];
    const float* be   = (const float*)d_in[8];
    const float* ltau = (const float*)d_in[9];
    const float* lal  = (const float*)d_in[10];
    float* out = (float*)d_out;

    k1_context<<<B_ * V_, 128>>>(obs, idx);
    k2_cell<<<(B_ * N_) / 8, 256>>>(obs, mask, idx, tn, Wm, bm, We, be, ltau, lal);
    k3_refr<<<B_ * (N_ / K3_NPB), K3_TPB>>>(idx, tn, out);
}